// round 15
// baseline (speedup 1.0000x reference)
#include <cuda_runtime.h>
#include <cuda_fp16.h>
#include <cstdint>
#include <math.h>

// Problem constants
#define Bn   4
#define Nn   2048
#define Dn   512
#define Hn   8
#define Mn   (Bn * Nn)      // 8192 rows
#define QKVT_N 2048
#define CAT_N  1024

// Scratch (device globals — allocation-free per harness rules)
__device__ half g_qkvt[Mn * QKVT_N];    // 32 MB
__device__ half g_cat [Mn * CAT_N];     // 16 MB
__device__ half g_xh  [Mn * Dn];        // 8 MB
__device__ half g_wqh [Dn * QKVT_N];    // 2 MB
__device__ half g_woh [CAT_N * Dn];     // 1 MB

__device__ __forceinline__ uint32_t h2u(half2 v) {
    return *reinterpret_cast<uint32_t*>(&v);
}
__device__ __forceinline__ uint32_t s2u(const void* p) {
    return (uint32_t)__cvta_generic_to_shared(p);
}

#define MMA_F16(d, a, b)                                                       \
    asm volatile(                                                              \
        "mma.sync.aligned.m16n8k16.row.col.f32.f16.f16.f32 "                   \
        "{%0,%1,%2,%3},{%4,%5,%6,%7},{%8,%9},{%0,%1,%2,%3};"                   \
        : "+f"((d)[0]), "+f"((d)[1]), "+f"((d)[2]), "+f"((d)[3])               \
        : "r"((a)[0]), "r"((a)[1]), "r"((a)[2]), "r"((a)[3]),                  \
          "r"((b)[0]), "r"((b)[1]))

#define MMA_F16H(d, a, b)                                                      \
    asm volatile(                                                              \
        "mma.sync.aligned.m16n8k16.row.col.f16.f16.f16.f16 "                   \
        "{%0,%1},{%2,%3,%4,%5},{%6,%7},{%0,%1};"                               \
        : "+r"((d)[0]), "+r"((d)[1])                                           \
        : "r"((a)[0]), "r"((a)[1]), "r"((a)[2]), "r"((a)[3]),                  \
          "r"((b)[0]), "r"((b)[1]))

#define EX2H2(d, s)                                                            \
    asm("ex2.approx.f16x2 %0, %1;" : "=r"(d) : "r"(s))

#define LDSM_X4(r, addr)                                                       \
    asm volatile("ldmatrix.sync.aligned.m8n8.x4.shared.b16 {%0,%1,%2,%3}, [%4];" \
        : "=r"((r)[0]), "=r"((r)[1]), "=r"((r)[2]), "=r"((r)[3]) : "r"(addr))

#define LDSM_X4_T(r, addr)                                                     \
    asm volatile("ldmatrix.sync.aligned.m8n8.x4.trans.shared.b16 {%0,%1,%2,%3}, [%4];" \
        : "=r"((r)[0]), "=r"((r)[1]), "=r"((r)[2]), "=r"((r)[3]) : "r"(addr))

#define CP16(saddr, gptr)                                                      \
    asm volatile("cp.async.cg.shared.global [%0], [%1], 16;"                   \
        :: "r"(saddr), "l"(gptr))
#define CP_COMMIT() asm volatile("cp.async.commit_group;")
#define CP_WAIT1()  asm volatile("cp.async.wait_group 1;")
#define CP_WAIT0()  asm volatile("cp.async.wait_group 0;")

// ---------------------------------------------------------------------------
// Fused float->half conversion of x, W_qkv, W_out (one launch).
// ---------------------------------------------------------------------------
__global__ __launch_bounds__(256) void cvt_all(
    const float* __restrict__ x, const float* __restrict__ wq,
    const float* __restrict__ wo)
{
    const int NX = Mn * Dn / 4;        // 1048576
    const int NQ = Dn * QKVT_N / 4;    // 262144
    int i = blockIdx.x * 256 + threadIdx.x;
    const float4* src; half* dst; int k;
    if (i < NX)            { src = (const float4*)x;  dst = g_xh;  k = i; }
    else if (i < NX + NQ)  { src = (const float4*)wq; dst = g_wqh; k = i - NX; }
    else                   { src = (const float4*)wo; dst = g_woh; k = i - NX - NQ; }
    float4 v = src[k];
    uint2 u = { h2u(__floats2half2_rn(v.x, v.y)),
                h2u(__floats2half2_rn(v.z, v.w)) };
    ((uint2*)dst)[k] = u;
}

// ---------------------------------------------------------------------------
// fp16 GEMM: C[M,N] = A[M,K] @ B[K,N] (+bias for float C).
// CTA tile 64x256, 8 warps of 32x64 (LDSM:MMA ratio preserved vs 64x64),
// K-chunks of 64, 2-stage cp.async pipeline, 2 CTAs/SM (16 warps/SM).
// As[m][k] ld=72, Bs[k][n] ld=264.
// ---------------------------------------------------------------------------
#define GBUF 43008u     // per-buffer bytes: As 64*72*2 + Bs 64*264*2
template<typename TC>
__global__ __launch_bounds__(256, 2) void gemm_h(
    const half* __restrict__ A, const half* __restrict__ B,
    TC* __restrict__ C, const float* __restrict__ bias,
    int M, int N, int K)
{
    extern __shared__ char smem[];
    const uint32_t sbase = s2u(smem);

    const int tid  = threadIdx.x;
    const int brow = blockIdx.y * 64;
    const int bcol = blockIdx.x * 256;

    // Loaders: A 2x CP16 (64 rows x 64 k), B 8x CP16 (64 rows x 256 n)
    const int a_r = tid >> 2, a_c0 = (tid & 3) * 16;
    const int b_r = tid >> 2, b_c0 = (tid & 3) * 64;

    const half* Aptr = A + (size_t)(brow + a_r) * K + a_c0;
    const half* Bptr = B + (size_t)b_r * N + bcol + b_c0;
    const uint32_t sAoff = (uint32_t)(a_r * 72 + a_c0) * 2;
    const uint32_t sBoff = 64u * 72u * 2u + (uint32_t)(b_r * 264 + b_c0) * 2;

    auto issue = [&](int c, int buf) {
        const half* ga = Aptr + c * 64;
        const half* gb = Bptr + (size_t)(c * 64) * N;
        uint32_t sa = sbase + buf * GBUF + sAoff;
        uint32_t sb = sbase + buf * GBUF + sBoff;
        CP16(sa,      ga);
        CP16(sa + 16, ga + 8);
        #pragma unroll
        for (int j = 0; j < 8; j++)
            CP16(sb + j * 16, gb + j * 8);
        CP_COMMIT();
    };

    const int warp = tid >> 5, lane = tid & 31;
    const int wm = warp >> 2, wn = warp & 3;   // 2 x 32 rows, 4 x 64 cols
    const int r0 = lane >> 2, c0 = lane & 3;
    const int lq = lane & 7, quad = lane >> 3;
    const int aRow = (quad & 1) * 8 + lq, aCol = (quad >> 1) * 8;
    const int bRow = (quad & 1) * 8 + lq, bCol = (quad >> 1) * 8;

    float acc[2][8][4];
    #pragma unroll
    for (int im = 0; im < 2; im++)
        #pragma unroll
        for (int jn = 0; jn < 8; jn++)
            #pragma unroll
            for (int q = 0; q < 4; q++) acc[im][jn][q] = 0.f;

    const int nc = K / 64;   // 8 or 16
    issue(0, 0);
    issue(1, 1);

    for (int c = 0; c < nc; c++) {
        if (c + 1 < nc) { CP_WAIT1(); } else { CP_WAIT0(); }
        __syncthreads();

        const uint32_t sAu = sbase + (c & 1) * GBUF;
        const uint32_t sBu = sAu + 64u * 72u * 2u;

        #pragma unroll
        for (int kk = 0; kk < 4; kk++) {
            uint32_t af[2][4];
            #pragma unroll
            for (int im = 0; im < 2; im++)
                LDSM_X4(af[im], sAu +
                    ((wm * 32 + im * 16 + aRow) * 72 + kk * 16 + aCol) * 2);
            #pragma unroll
            for (int jnp = 0; jnp < 4; jnp++) {
                uint32_t bf[4];
                LDSM_X4_T(bf, sBu +
                    ((kk * 16 + bRow) * 264 + wn * 64 + jnp * 16 + bCol) * 2);
                #pragma unroll
                for (int im = 0; im < 2; im++) {
                    MMA_F16(acc[im][2 * jnp    ], af[im], bf);
                    MMA_F16(acc[im][2 * jnp + 1], af[im], bf + 2);
                }
            }
        }
        __syncthreads();
        if (c + 2 < nc) issue(c + 2, c & 1);
    }

    // Epilogue
    #pragma unroll
    for (int jn = 0; jn < 8; jn++) {
        const int col = bcol + wn * 64 + jn * 8 + 2 * c0;
        float bx = 0.f, by = 0.f;
        if (bias) { bx = bias[col]; by = bias[col + 1]; }
        #pragma unroll
        for (int im = 0; im < 2; im++) {
            const int row = brow + wm * 32 + im * 16 + r0;
            if constexpr (sizeof(TC) == 4) {
                float2 v0 = { acc[im][jn][0] + bx, acc[im][jn][1] + by };
                float2 v1 = { acc[im][jn][2] + bx, acc[im][jn][3] + by };
                *(float2*)&C[(size_t)row       * N + col] = v0;
                *(float2*)&C[(size_t)(row + 8) * N + col] = v1;
            } else {
                *(half2*)&C[(size_t)row       * N + col] =
                    __floats2half2_rn(acc[im][jn][0], acc[im][jn][1]);
                *(half2*)&C[(size_t)(row + 8) * N + col] =
                    __floats2half2_rn(acc[im][jn][2], acc[im][jn][3]);
            }
        }
    }
}

// ---------------------------------------------------------------------------
// Fused flash attention + decay scan (unchanged from the 194.6us build).
// Blocks 0..511: flash, 8 warps x 16 rows (BR=128), BC=64, Q prescaled
// by log2e/8, fp16 S accumulators, ex2 on packed S, constant ones b-frag.
// K/V in a 3-buffer cp.async ring with issue-ahead 1 -> SINGLE sync/iter.
// Blocks 512..767: branch-2 scan (fills flash's ragged tail).
// Dynamic smem (55296 B), 2 CTAs/SM.
// ---------------------------------------------------------------------------
#define FK_STRIDE (64 * 72)              // halves per K buffer
#define FBUF_OFF  (3 * FK_STRIDE)        // Vs base (halves)
#define FSM_BYTES (2 * 2 * FBUF_OFF)     // 55296 B
__global__ __launch_bounds__(256, 2) void flash_scan(
    const half* __restrict__ qkvt, half* __restrict__ cat)
{
    extern __shared__ half fsm[];

    const int tid = threadIdx.x;

    if (blockIdx.x < 512) {
        // ================= FLASH =================
        half* Ksm = fsm;                  // [3][64][72]
        half* Vsm = fsm + FBUF_OFF;       // [3][64][72]

        const int warp = tid >> 5, lane = tid & 31;
        const int r0 = lane >> 2, c0 = lane & 3;
        const int lq = lane & 7, quad = lane >> 3;
        const int bh = blockIdx.x >> 4;
        const int b  = bh >> 3, h = bh & 7;
        const int i0 = (blockIdx.x & 15) * 128;

        const size_t rowbase = (size_t)b * Nn;
        const half* Qg = qkvt + (rowbase + i0) * QKVT_N + h * 64;
        const half* Kg = qkvt + rowbase * QKVT_N + 512  + h * 64;
        const half* Vg = qkvt + rowbase * QKVT_N + 1024 + h * 64;

        const int rA = warp * 16 + r0;

        const half2 sc = __float2half2_rn(0.18033688011112042f);   // log2e/8
        uint32_t q[4][4];
        #pragma unroll
        for (int kk = 0; kk < 4; kk++) {
            const int col = kk * 16 + 2 * c0;
            q[kk][0] = h2u(__hmul2(*(const half2*)(Qg + (size_t)rA * QKVT_N + col), sc));
            q[kk][1] = h2u(__hmul2(*(const half2*)(Qg + (size_t)(rA + 8) * QKVT_N + col), sc));
            q[kk][2] = h2u(__hmul2(*(const half2*)(Qg + (size_t)rA * QKVT_N + col + 8), sc));
            q[kk][3] = h2u(__hmul2(*(const half2*)(Qg + (size_t)(rA + 8) * QKVT_N + col + 8), sc));
        }

        float o[8][4];
        #pragma unroll
        for (int jn = 0; jn < 8; jn++)
            #pragma unroll
            for (int p = 0; p < 4; p++) o[jn][p] = 0.f;
        float ol[4] = {0.f, 0.f, 0.f, 0.f};

        const uint32_t blv = (r0 == 0) ? 0x3C003C00u : 0u;
        const uint32_t blf[2] = { blv, blv };

        const int kr = tid >> 3, kc8 = (tid & 7) * 8;
        auto issueKV = [&](int kt, int bufi) {
            #pragma unroll
            for (int it = 0; it < 2; it++) {
                int r = kr + it * 32;
                CP16(s2u(Ksm + (bufi * 64 + r) * 72 + kc8),
                     Kg + (size_t)(kt + r) * QKVT_N + kc8);
                CP16(s2u(Vsm + (bufi * 64 + r) * 72 + kc8),
                     Vg + (size_t)(kt + r) * QKVT_N + kc8);
            }
            CP_COMMIT();
        };

        const int kRow = (quad >= 2 ? 8 : 0) + lq, kCol = (quad & 1) * 8;
        const int vRow = (quad & 1) * 8 + lq,      vCol = (quad >> 1) * 8;

        issueKV(0, 0);

        const int NT = Nn / 64;
        int bu = 0;
        for (int it = 0; it < NT; it++) {
            if (it + 1 < NT) {
                int nb = bu + 1; if (nb == 3) nb = 0;
                issueKV((it + 1) * 64, nb);
                CP_WAIT1();
            } else {
                CP_WAIT0();
            }
            __syncthreads();   // single barrier per tile

            const half* Kb = Ksm + bu * FK_STRIDE;
            const half* Vb = Vsm + bu * FK_STRIDE;

            uint32_t sh[8][2];
            #pragma unroll
            for (int jn = 0; jn < 8; jn++) { sh[jn][0] = 0u; sh[jn][1] = 0u; }

            #pragma unroll
            for (int kk = 0; kk < 4; kk++) {
                const int kc = kk * 16;
                #pragma unroll
                for (int jnp = 0; jnp < 4; jnp++) {
                    uint32_t bf[4];
                    LDSM_X4(bf, s2u(Kb + (jnp * 16 + kRow) * 72 + kc + kCol));
                    MMA_F16H(sh[2 * jnp    ], q[kk], bf);
                    MMA_F16H(sh[2 * jnp + 1], q[kk], bf + 2);
                }
            }

            uint32_t ph[4][4];
            #pragma unroll
            for (int jnp = 0; jnp < 4; jnp++) {
                EX2H2(ph[jnp][0], sh[2 * jnp    ][0]);
                EX2H2(ph[jnp][1], sh[2 * jnp    ][1]);
                EX2H2(ph[jnp][2], sh[2 * jnp + 1][0]);
                EX2H2(ph[jnp][3], sh[2 * jnp + 1][1]);
            }

            #pragma unroll
            for (int kk2 = 0; kk2 < 4; kk2++) {
                const int kc2 = kk2 * 16;
                #pragma unroll
                for (int jnp = 0; jnp < 4; jnp++) {
                    uint32_t bf[4];
                    LDSM_X4_T(bf, s2u(Vb + (kc2 + vRow) * 72 + jnp * 16 + vCol));
                    MMA_F16(o[2 * jnp    ], ph[kk2], bf);
                    MMA_F16(o[2 * jnp + 1], ph[kk2], bf + 2);
                }
                MMA_F16(ol, ph[kk2], blf);
            }

            if (++bu == 3) bu = 0;
        }

        const float lA = __shfl_sync(0xffffffffu, ol[0], lane & ~3);
        const float lB = __shfl_sync(0xffffffffu, ol[2], lane & ~3);
        const float invA = 1.0f / lA, invB = 1.0f / lB;
        half* outp = cat + (rowbase + i0 + rA) * CAT_N + h * 128;
        #pragma unroll
        for (int jn = 0; jn < 8; jn++) {
            const int col = jn * 8 + 2 * c0;
            *(half2*)&outp[col] =
                __floats2half2_rn(o[jn][0] * invA, o[jn][1] * invA);
            *(half2*)&outp[(size_t)8 * CAT_N + col] =
                __floats2half2_rn(o[jn][2] * invB, o[jn][3] * invB);
        }
    } else {
        // ================= SCAN =================
        float* rs = (float*)fsm;            // [192]
        half*  us = fsm + 384;              // [64][256]

        const int bid2 = blockIdx.x - 512;               // 0..255
        const int chunk = (bid2 * 256) >> 11;            // constant per block
        const int c0 = chunk * 64;
        const int jbase = c0 - 64;

        const float la = -0.36787944117144233f;
        const float a  =  0.6922006275553464f;
        const float g  = a / (1.f - a);
        for (int t = tid; t < 192; t += 256) {
            int j = jbase + t;
            if (j >= 0 && j < Nn) {
                float s = 1.f + g * (1.f - __expf(la * (float)j))
                              + g * (1.f - __expf(la * (float)(Nn - 1 - j)));
                rs[t] = 1.f / s;
            }
        }
        __syncthreads();

        const int id    = bid2 * 256 + tid;
        const int colid = id & 2047;
        const int b = colid >> 9;
        const int f = colid & 511;
        const int h = f >> 6, d = f & 63;

        const half* tcol = qkvt + (size_t)b * Nn * QKVT_N + 1536 + f;
        half*       ocol = cat  + (size_t)b * Nn * CAT_N + h * 128 + 64 + d;

        float fwd[64];
        float acc = 0.f;
        #pragma unroll
        for (int i = 0; i < 64; i++) {            // fwd halo
            int j = c0 - 64 + i;
            float u = 0.f;
            if (j >= 0) u = rs[i] * __half2float(tcol[(size_t)j * QKVT_N]);
            acc = fmaf(a, acc, u);
        }
        #pragma unroll
        for (int i = 0; i < 64; i++) {            // fwd main; stage u in smem
            float u = rs[64 + i] * __half2float(tcol[(size_t)(c0 + i) * QKVT_N]);
            us[i * 256 + tid] = __float2half(u);
            acc = fmaf(a, acc, u);
            fwd[i] = acc;
        }
        acc = 0.f;
        #pragma unroll
        for (int i = 63; i >= 0; i--) {           // bwd halo
            int j = c0 + 64 + i;
            float u = 0.f;
            if (j < Nn) u = rs[128 + i] * __half2float(tcol[(size_t)j * QKVT_N]);
            acc = fmaf(a, acc, u);
        }
        #pragma unroll
        for (int i = 63; i >= 0; i--) {           // bwd main + single write
            float prev = acc;
            ocol[(size_t)(c0 + i) * CAT_N] = __float2half(fwd[i] + a * prev);
            acc = fmaf(a, acc, __half2float(us[i * 256 + tid]));
        }
    }
}

// ---------------------------------------------------------------------------
extern "C" void kernel_launch(void* const* d_in, const int* in_sizes, int n_in,
                              void* d_out, int out_size)
{
    const float* x    = (const float*)d_in[0];   // [4,2048,512]
    const float* Wqkv = (const float*)d_in[1];   // [512,2048]
    const float* Wout = (const float*)d_in[2];   // [1024,512]
    const float* bout = (const float*)d_in[3];   // [512]
    float* out = (float*)d_out;                  // [4,2048,512]

    half *qkvt, *cat, *xh, *wqh, *woh;
    cudaGetSymbolAddress((void**)&qkvt, g_qkvt);
    cudaGetSymbolAddress((void**)&cat,  g_cat);
    cudaGetSymbolAddress((void**)&xh,   g_xh);
    cudaGetSymbolAddress((void**)&wqh,  g_wqh);
    cudaGetSymbolAddress((void**)&woh,  g_woh);

    // Convert all fp32 inputs to half (one launch)
    cvt_all<<<(Mn * Dn + Dn * QKVT_N + CAT_N * Dn) / 4 / 256, 256>>>(
        x, Wqkv, Wout);

    const int GS = 2 * GBUF;   // 86016 B dynamic smem, 2 CTAs/SM
    cudaFuncSetAttribute(gemm_h<half>,
                         cudaFuncAttributeMaxDynamicSharedMemorySize, GS);
    cudaFuncSetAttribute(gemm_h<float>,
                         cudaFuncAttributeMaxDynamicSharedMemorySize, GS);
    cudaFuncSetAttribute(flash_scan,
                         cudaFuncAttributeMaxDynamicSharedMemorySize, FSM_BYTES);

    // GEMM1: QKVT(half) = Xh @ Wqkvh
    gemm_h<half><<<dim3(QKVT_N / 256, Mn / 64), 256, GS>>>(
        xh, wqh, qkvt, nullptr, Mn, QKVT_N, Dn);

    // Branch 1 + Branch 2 fused: flash (blocks 0..511) + scan (512..767)
    flash_scan<<<768, 256, FSM_BYTES>>>(qkvt, cat);

    // GEMM2: out(float) = cat(half) @ Wouth + b_out
    gemm_h<float><<<dim3(Dn / 256, Mn / 64), 256, GS>>>(
        cat, woh, out, bout, Mn, Dn, CAT_N);
}

// round 16
// speedup vs baseline: 1.3371x; 1.3371x over previous
#include <cuda_runtime.h>
#include <cuda_fp16.h>
#include <cstdint>
#include <math.h>

// Problem constants
#define Bn   4
#define Nn   2048
#define Dn   512
#define Hn   8
#define Mn   (Bn * Nn)      // 8192 rows
#define QKVT_N 2048
#define CAT_N  1024

// Scratch (device globals — allocation-free per harness rules)
__device__ half g_qkvt[Mn * QKVT_N];    // 32 MB
__device__ half g_cat [Mn * CAT_N];     // 16 MB
__device__ half g_xh  [Mn * Dn];        // 8 MB
__device__ half g_wqh [Dn * QKVT_N];    // 2 MB
__device__ half g_woh [CAT_N * Dn];     // 1 MB

__device__ __forceinline__ uint32_t h2u(half2 v) {
    return *reinterpret_cast<uint32_t*>(&v);
}
__device__ __forceinline__ uint32_t s2u(const void* p) {
    return (uint32_t)__cvta_generic_to_shared(p);
}

#define MMA_F16(d, a, b)                                                       \
    asm volatile(                                                              \
        "mma.sync.aligned.m16n8k16.row.col.f32.f16.f16.f32 "                   \
        "{%0,%1,%2,%3},{%4,%5,%6,%7},{%8,%9},{%0,%1,%2,%3};"                   \
        : "+f"((d)[0]), "+f"((d)[1]), "+f"((d)[2]), "+f"((d)[3])               \
        : "r"((a)[0]), "r"((a)[1]), "r"((a)[2]), "r"((a)[3]),                  \
          "r"((b)[0]), "r"((b)[1]))

#define MMA_F16H(d, a, b)                                                      \
    asm volatile(                                                              \
        "mma.sync.aligned.m16n8k16.row.col.f16.f16.f16.f16 "                   \
        "{%0,%1},{%2,%3,%4,%5},{%6,%7},{%0,%1};"                               \
        : "+r"((d)[0]), "+r"((d)[1])                                           \
        : "r"((a)[0]), "r"((a)[1]), "r"((a)[2]), "r"((a)[3]),                  \
          "r"((b)[0]), "r"((b)[1]))

#define EX2H2(d, s)                                                            \
    asm("ex2.approx.f16x2 %0, %1;" : "=r"(d) : "r"(s))

#define LDSM_X4(r, addr)                                                       \
    asm volatile("ldmatrix.sync.aligned.m8n8.x4.shared.b16 {%0,%1,%2,%3}, [%4];" \
        : "=r"((r)[0]), "=r"((r)[1]), "=r"((r)[2]), "=r"((r)[3]) : "r"(addr))

#define LDSM_X4_T(r, addr)                                                     \
    asm volatile("ldmatrix.sync.aligned.m8n8.x4.trans.shared.b16 {%0,%1,%2,%3}, [%4];" \
        : "=r"((r)[0]), "=r"((r)[1]), "=r"((r)[2]), "=r"((r)[3]) : "r"(addr))

#define CP16(saddr, gptr)                                                      \
    asm volatile("cp.async.cg.shared.global [%0], [%1], 16;"                   \
        :: "r"(saddr), "l"(gptr))
#define CP_COMMIT() asm volatile("cp.async.commit_group;")
#define CP_WAIT2()  asm volatile("cp.async.wait_group 2;")
#define CP_WAIT1()  asm volatile("cp.async.wait_group 1;")
#define CP_WAIT0()  asm volatile("cp.async.wait_group 0;")

// ---------------------------------------------------------------------------
// Fused float->half conversion of x, W_qkv, W_out (one launch).
// ---------------------------------------------------------------------------
__global__ __launch_bounds__(256) void cvt_all(
    const float* __restrict__ x, const float* __restrict__ wq,
    const float* __restrict__ wo)
{
    const int NX = Mn * Dn / 4;        // 1048576
    const int NQ = Dn * QKVT_N / 4;    // 262144
    int i = blockIdx.x * 256 + threadIdx.x;
    const float4* src; half* dst; int k;
    if (i < NX)            { src = (const float4*)x;  dst = g_xh;  k = i; }
    else if (i < NX + NQ)  { src = (const float4*)wq; dst = g_wqh; k = i - NX; }
    else                   { src = (const float4*)wo; dst = g_woh; k = i - NX - NQ; }
    float4 v = src[k];
    uint2 u = { h2u(__floats2half2_rn(v.x, v.y)),
                h2u(__floats2half2_rn(v.z, v.w)) };
    ((uint2*)dst)[k] = u;
}

// ---------------------------------------------------------------------------
// fp16 GEMM: C[M,N] = A[M,K] @ B[K,N] (+bias for float C).
// Block tile 128x256, 8 warps of 64x64, K-chunks of 64.
// 4-buffer cp.async pipeline, issue-ahead 2, SINGLE sync per chunk.
// Fragment LDSMs software-pipelined one kk ahead (latency hiding).
// As[m][k] ld=72, Bs[k][n] ld=264.
// ---------------------------------------------------------------------------
#define GBUF 52224u     // per-buffer bytes: As 128*72*2 + Bs 64*264*2
template<typename TC>
__global__ __launch_bounds__(256, 1) void gemm_h(
    const half* __restrict__ A, const half* __restrict__ B,
    TC* __restrict__ C, const float* __restrict__ bias,
    int M, int N, int K)
{
    extern __shared__ char smem[];
    const uint32_t sbase = s2u(smem);

    const int tid  = threadIdx.x;
    const int brow = blockIdx.y * 128;
    const int bcol = blockIdx.x * 256;

    const int a_r = tid >> 3, a_c = (tid & 7) * 8;
    const int b_r = tid >> 5, b_c = (tid & 31) * 8;

    const half* Aptr = A + (size_t)(brow + a_r) * K + a_c;
    const half* Bptr = B + (size_t)b_r * N + bcol + b_c;
    const uint32_t sAoff = (uint32_t)(a_r * 72 + a_c) * 2;
    const uint32_t sBoff = 128u * 72u * 2u + (uint32_t)(b_r * 264 + b_c) * 2;

    auto issue = [&](int c, int buf) {
        const half* ga = Aptr + c * 64;
        uint32_t sa = sbase + buf * GBUF + sAoff;
        #pragma unroll
        for (int i = 0; i < 4; i++)
            CP16(sa + i * (32 * 72 * 2), ga + (size_t)(32 * i) * K);
        const half* gb = Bptr + (size_t)(c * 64) * N;
        uint32_t sb = sbase + buf * GBUF + sBoff;
        #pragma unroll
        for (int i = 0; i < 8; i++)
            CP16(sb + i * (8 * 264 * 2), gb + (size_t)(8 * i) * N);
        CP_COMMIT();
    };

    const int warp = tid >> 5, lane = tid & 31;
    const int wm = warp >> 2, wn = warp & 3;
    const int r0 = lane >> 2, c0 = lane & 3;
    const int lq = lane & 7, quad = lane >> 3;
    const int aRow = (quad & 1) * 8 + lq, aCol = (quad >> 1) * 8;
    const int bRow = (quad & 1) * 8 + lq, bCol = (quad >> 1) * 8;

    float acc[4][8][4];
    #pragma unroll
    for (int im = 0; im < 4; im++)
        #pragma unroll
        for (int jn = 0; jn < 8; jn++)
            #pragma unroll
            for (int q = 0; q < 4; q++) acc[im][jn][q] = 0.f;

    const int nc = K / 64;   // 8 or 16
    issue(0, 0);
    issue(1, 1);

    for (int c = 0; c < nc; c++) {
        if (c + 2 < nc) { issue(c + 2, (c + 2) & 3); CP_WAIT2(); }
        else if (c + 1 < nc) { CP_WAIT1(); }
        else { CP_WAIT0(); }
        __syncthreads();   // single barrier per chunk

        const uint32_t sAu = sbase + (c & 3) * GBUF;
        const uint32_t sBu = sAu + 128u * 72u * 2u;

        // Software-pipelined fragment loads: kk+1 LDSMs issued before kk MMAs.
        uint32_t af[2][4][4], bf[2][2][4];
        #pragma unroll
        for (int im = 0; im < 4; im++)
            LDSM_X4(af[0][im], sAu +
                ((wm * 64 + im * 16 + aRow) * 72 + aCol) * 2);
        #pragma unroll
        for (int jp = 0; jp < 2; jp++)
            LDSM_X4_T(bf[0][jp], sBu +
                (bRow * 264 + wn * 64 + jp * 32 + bCol) * 2);

        #pragma unroll
        for (int kk = 0; kk < 4; kk++) {
            const int cur = kk & 1, nxt = cur ^ 1;
            if (kk < 3) {
                const int kc = (kk + 1) * 16;
                #pragma unroll
                for (int im = 0; im < 4; im++)
                    LDSM_X4(af[nxt][im], sAu +
                        ((wm * 64 + im * 16 + aRow) * 72 + kc + aCol) * 2);
                #pragma unroll
                for (int jp = 0; jp < 2; jp++)
                    LDSM_X4_T(bf[nxt][jp], sBu +
                        ((kc + bRow) * 264 + wn * 64 + jp * 32 + bCol) * 2);
            }
            #pragma unroll
            for (int jp = 0; jp < 2; jp++)
                #pragma unroll
                for (int hb = 0; hb < 2; hb++) {
                    const int jn = jp * 4 + hb * 2;
                    #pragma unroll
                    for (int im = 0; im < 4; im++) {
                        MMA_F16(acc[im][jn    ], af[cur][im], bf[cur][jp] + 2 * hb);
                        MMA_F16(acc[im][jn + 1], af[cur][im], bf[cur][jp] + 2 * hb);
                    }
                }
        }
    }

    // (fixup: the loop above accumulates column pairs; see corrected below)
    // NOTE: structure kept identical to R14 semantics via jn mapping:
    //   bf[jp] holds 16 columns (two 8-col halves at +0 and +2).

    // Epilogue
    #pragma unroll
    for (int jn = 0; jn < 8; jn++) {
        const int col = bcol + wn * 64 + jn * 8 + 2 * c0;
        float bx = 0.f, by = 0.f;
        if (bias) { bx = bias[col]; by = bias[col + 1]; }
        #pragma unroll
        for (int im = 0; im < 4; im++) {
            const int row = brow + wm * 64 + im * 16 + r0;
            if constexpr (sizeof(TC) == 4) {
                float2 v0 = { acc[im][jn][0] + bx, acc[im][jn][1] + by };
                float2 v1 = { acc[im][jn][2] + bx, acc[im][jn][3] + by };
                *(float2*)&C[(size_t)row       * N + col] = v0;
                *(float2*)&C[(size_t)(row + 8) * N + col] = v1;
            } else {
                *(half2*)&C[(size_t)row       * N + col] =
                    __floats2half2_rn(acc[im][jn][0], acc[im][jn][1]);
                *(half2*)&C[(size_t)(row + 8) * N + col] =
                    __floats2half2_rn(acc[im][jn][2], acc[im][jn][3]);
            }
        }
    }
}

// Correct MMA mapping: replace flawed inner block above via template
// specialization is not possible inline; the kernel below is the one used.
// ---------------------------------------------------------------------------
template<typename TC>
__global__ __launch_bounds__(256, 1) void gemm_h2(
    const half* __restrict__ A, const half* __restrict__ B,
    TC* __restrict__ C, const float* __restrict__ bias,
    int M, int N, int K)
{
    extern __shared__ char smem[];
    const uint32_t sbase = s2u(smem);

    const int tid  = threadIdx.x;
    const int brow = blockIdx.y * 128;
    const int bcol = blockIdx.x * 256;

    const int a_r = tid >> 3, a_c = (tid & 7) * 8;
    const int b_r = tid >> 5, b_c = (tid & 31) * 8;

    const half* Aptr = A + (size_t)(brow + a_r) * K + a_c;
    const half* Bptr = B + (size_t)b_r * N + bcol + b_c;
    const uint32_t sAoff = (uint32_t)(a_r * 72 + a_c) * 2;
    const uint32_t sBoff = 128u * 72u * 2u + (uint32_t)(b_r * 264 + b_c) * 2;

    auto issue = [&](int c, int buf) {
        const half* ga = Aptr + c * 64;
        uint32_t sa = sbase + buf * GBUF + sAoff;
        #pragma unroll
        for (int i = 0; i < 4; i++)
            CP16(sa + i * (32 * 72 * 2), ga + (size_t)(32 * i) * K);
        const half* gb = Bptr + (size_t)(c * 64) * N;
        uint32_t sb = sbase + buf * GBUF + sBoff;
        #pragma unroll
        for (int i = 0; i < 8; i++)
            CP16(sb + i * (8 * 264 * 2), gb + (size_t)(8 * i) * N);
        CP_COMMIT();
    };

    const int warp = tid >> 5, lane = tid & 31;
    const int wm = warp >> 2, wn = warp & 3;
    const int r0 = lane >> 2, c0 = lane & 3;
    const int lq = lane & 7, quad = lane >> 3;
    const int aRow = (quad & 1) * 8 + lq, aCol = (quad >> 1) * 8;
    const int bRow = (quad & 1) * 8 + lq, bCol = (quad >> 1) * 8;

    float acc[4][8][4];
    #pragma unroll
    for (int im = 0; im < 4; im++)
        #pragma unroll
        for (int jn = 0; jn < 8; jn++)
            #pragma unroll
            for (int q = 0; q < 4; q++) acc[im][jn][q] = 0.f;

    const int nc = K / 64;
    issue(0, 0);
    issue(1, 1);

    for (int c = 0; c < nc; c++) {
        if (c + 2 < nc) { issue(c + 2, (c + 2) & 3); CP_WAIT2(); }
        else if (c + 1 < nc) { CP_WAIT1(); }
        else { CP_WAIT0(); }
        __syncthreads();

        const uint32_t sAu = sbase + (c & 3) * GBUF;
        const uint32_t sBu = sAu + 128u * 72u * 2u;

        // Prefetch kk=0 fragments
        uint32_t af[2][4][4];
        uint32_t bf[2][4][4];   // [buf][jnp][4] : jnp covers 16 cols each
        #pragma unroll
        for (int im = 0; im < 4; im++)
            LDSM_X4(af[0][im], sAu + ((wm * 64 + im * 16 + aRow) * 72 + aCol) * 2);
        #pragma unroll
        for (int jnp = 0; jnp < 4; jnp++)
            LDSM_X4_T(bf[0][jnp], sBu +
                (bRow * 264 + wn * 64 + jnp * 16 + bCol) * 2);

        #pragma unroll
        for (int kk = 0; kk < 4; kk++) {
            const int cur = kk & 1, nxt = cur ^ 1;
            if (kk < 3) {
                const int kc = (kk + 1) * 16;
                #pragma unroll
                for (int im = 0; im < 4; im++)
                    LDSM_X4(af[nxt][im], sAu +
                        ((wm * 64 + im * 16 + aRow) * 72 + kc + aCol) * 2);
                #pragma unroll
                for (int jnp = 0; jnp < 4; jnp++)
                    LDSM_X4_T(bf[nxt][jnp], sBu +
                        ((kc + bRow) * 264 + wn * 64 + jnp * 16 + bCol) * 2);
            }
            #pragma unroll
            for (int jnp = 0; jnp < 4; jnp++)
                #pragma unroll
                for (int im = 0; im < 4; im++) {
                    MMA_F16(acc[im][2 * jnp    ], af[cur][im], bf[cur][jnp]);
                    MMA_F16(acc[im][2 * jnp + 1], af[cur][im], bf[cur][jnp] + 2);
                }
        }
    }

    // Epilogue
    #pragma unroll
    for (int jn = 0; jn < 8; jn++) {
        const int col = bcol + wn * 64 + jn * 8 + 2 * c0;
        float bx = 0.f, by = 0.f;
        if (bias) { bx = bias[col]; by = bias[col + 1]; }
        #pragma unroll
        for (int im = 0; im < 4; im++) {
            const int row = brow + wm * 64 + im * 16 + r0;
            if constexpr (sizeof(TC) == 4) {
                float2 v0 = { acc[im][jn][0] + bx, acc[im][jn][1] + by };
                float2 v1 = { acc[im][jn][2] + bx, acc[im][jn][3] + by };
                *(float2*)&C[(size_t)row       * N + col] = v0;
                *(float2*)&C[(size_t)(row + 8) * N + col] = v1;
            } else {
                *(half2*)&C[(size_t)row       * N + col] =
                    __floats2half2_rn(acc[im][jn][0], acc[im][jn][1]);
                *(half2*)&C[(size_t)(row + 8) * N + col] =
                    __floats2half2_rn(acc[im][jn][2], acc[im][jn][3]);
            }
        }
    }
}

// ---------------------------------------------------------------------------
// Fused flash attention + decay scan (unchanged from the 194.6us build).
// ---------------------------------------------------------------------------
#define FK_STRIDE (64 * 72)
#define FBUF_OFF  (3 * FK_STRIDE)
#define FSM_BYTES (2 * 2 * FBUF_OFF)     // 55296 B
__global__ __launch_bounds__(256, 2) void flash_scan(
    const half* __restrict__ qkvt, half* __restrict__ cat)
{
    extern __shared__ half fsm[];

    const int tid = threadIdx.x;

    if (blockIdx.x < 512) {
        // ================= FLASH =================
        half* Ksm = fsm;
        half* Vsm = fsm + FBUF_OFF;

        const int warp = tid >> 5, lane = tid & 31;
        const int r0 = lane >> 2, c0 = lane & 3;
        const int lq = lane & 7, quad = lane >> 3;
        const int bh = blockIdx.x >> 4;
        const int b  = bh >> 3, h = bh & 7;
        const int i0 = (blockIdx.x & 15) * 128;

        const size_t rowbase = (size_t)b * Nn;
        const half* Qg = qkvt + (rowbase + i0) * QKVT_N + h * 64;
        const half* Kg = qkvt + rowbase * QKVT_N + 512  + h * 64;
        const half* Vg = qkvt + rowbase * QKVT_N + 1024 + h * 64;

        const int rA = warp * 16 + r0;

        const half2 sc = __float2half2_rn(0.18033688011112042f);
        uint32_t q[4][4];
        #pragma unroll
        for (int kk = 0; kk < 4; kk++) {
            const int col = kk * 16 + 2 * c0;
            q[kk][0] = h2u(__hmul2(*(const half2*)(Qg + (size_t)rA * QKVT_N + col), sc));
            q[kk][1] = h2u(__hmul2(*(const half2*)(Qg + (size_t)(rA + 8) * QKVT_N + col), sc));
            q[kk][2] = h2u(__hmul2(*(const half2*)(Qg + (size_t)rA * QKVT_N + col + 8), sc));
            q[kk][3] = h2u(__hmul2(*(const half2*)(Qg + (size_t)(rA + 8) * QKVT_N + col + 8), sc));
        }

        float o[8][4];
        #pragma unroll
        for (int jn = 0; jn < 8; jn++)
            #pragma unroll
            for (int p = 0; p < 4; p++) o[jn][p] = 0.f;
        float ol[4] = {0.f, 0.f, 0.f, 0.f};

        const uint32_t blv = (r0 == 0) ? 0x3C003C00u : 0u;
        const uint32_t blf[2] = { blv, blv };

        const int kr = tid >> 3, kc8 = (tid & 7) * 8;
        auto issueKV = [&](int kt, int bufi) {
            #pragma unroll
            for (int it = 0; it < 2; it++) {
                int r = kr + it * 32;
                CP16(s2u(Ksm + (bufi * 64 + r) * 72 + kc8),
                     Kg + (size_t)(kt + r) * QKVT_N + kc8);
                CP16(s2u(Vsm + (bufi * 64 + r) * 72 + kc8),
                     Vg + (size_t)(kt + r) * QKVT_N + kc8);
            }
            CP_COMMIT();
        };

        const int kRow = (quad >= 2 ? 8 : 0) + lq, kCol = (quad & 1) * 8;
        const int vRow = (quad & 1) * 8 + lq,      vCol = (quad >> 1) * 8;

        issueKV(0, 0);

        const int NT = Nn / 64;
        int bu = 0;
        for (int it = 0; it < NT; it++) {
            if (it + 1 < NT) {
                int nb = bu + 1; if (nb == 3) nb = 0;
                issueKV((it + 1) * 64, nb);
                CP_WAIT1();
            } else {
                CP_WAIT0();
            }
            __syncthreads();

            const half* Kb = Ksm + bu * FK_STRIDE;
            const half* Vb = Vsm + bu * FK_STRIDE;

            uint32_t sh[8][2];
            #pragma unroll
            for (int jn = 0; jn < 8; jn++) { sh[jn][0] = 0u; sh[jn][1] = 0u; }

            #pragma unroll
            for (int kk = 0; kk < 4; kk++) {
                const int kc = kk * 16;
                #pragma unroll
                for (int jnp = 0; jnp < 4; jnp++) {
                    uint32_t bfk[4];
                    LDSM_X4(bfk, s2u(Kb + (jnp * 16 + kRow) * 72 + kc + kCol));
                    MMA_F16H(sh[2 * jnp    ], q[kk], bfk);
                    MMA_F16H(sh[2 * jnp + 1], q[kk], bfk + 2);
                }
            }

            uint32_t ph[4][4];
            #pragma unroll
            for (int jnp = 0; jnp < 4; jnp++) {
                EX2H2(ph[jnp][0], sh[2 * jnp    ][0]);
                EX2H2(ph[jnp][1], sh[2 * jnp    ][1]);
                EX2H2(ph[jnp][2], sh[2 * jnp + 1][0]);
                EX2H2(ph[jnp][3], sh[2 * jnp + 1][1]);
            }

            #pragma unroll
            for (int kk2 = 0; kk2 < 4; kk2++) {
                const int kc2 = kk2 * 16;
                #pragma unroll
                for (int jnp = 0; jnp < 4; jnp++) {
                    uint32_t bfv[4];
                    LDSM_X4_T(bfv, s2u(Vb + (kc2 + vRow) * 72 + jnp * 16 + vCol));
                    MMA_F16(o[2 * jnp    ], ph[kk2], bfv);
                    MMA_F16(o[2 * jnp + 1], ph[kk2], bfv + 2);
                }
                MMA_F16(ol, ph[kk2], blf);
            }

            if (++bu == 3) bu = 0;
        }

        const float lA = __shfl_sync(0xffffffffu, ol[0], lane & ~3);
        const float lB = __shfl_sync(0xffffffffu, ol[2], lane & ~3);
        const float invA = 1.0f / lA, invB = 1.0f / lB;
        half* outp = cat + (rowbase + i0 + rA) * CAT_N + h * 128;
        #pragma unroll
        for (int jn = 0; jn < 8; jn++) {
            const int col = jn * 8 + 2 * c0;
            *(half2*)&outp[col] =
                __floats2half2_rn(o[jn][0] * invA, o[jn][1] * invA);
            *(half2*)&outp[(size_t)8 * CAT_N + col] =
                __floats2half2_rn(o[jn][2] * invB, o[jn][3] * invB);
        }
    } else {
        // ================= SCAN =================
        float* rs = (float*)fsm;
        half*  us = fsm + 384;

        const int bid2 = blockIdx.x - 512;
        const int chunk = (bid2 * 256) >> 11;
        const int c0 = chunk * 64;
        const int jbase = c0 - 64;

        const float la = -0.36787944117144233f;
        const float a  =  0.6922006275553464f;
        const float g  = a / (1.f - a);
        for (int t = tid; t < 192; t += 256) {
            int j = jbase + t;
            if (j >= 0 && j < Nn) {
                float s = 1.f + g * (1.f - __expf(la * (float)j))
                              + g * (1.f - __expf(la * (float)(Nn - 1 - j)));
                rs[t] = 1.f / s;
            }
        }
        __syncthreads();

        const int id    = bid2 * 256 + tid;
        const int colid = id & 2047;
        const int b = colid >> 9;
        const int f = colid & 511;
        const int h = f >> 6, d = f & 63;

        const half* tcol = qkvt + (size_t)b * Nn * QKVT_N + 1536 + f;
        half*       ocol = cat  + (size_t)b * Nn * CAT_N + h * 128 + 64 + d;

        float fwd[64];
        float acc = 0.f;
        #pragma unroll
        for (int i = 0; i < 64; i++) {
            int j = c0 - 64 + i;
            float u = 0.f;
            if (j >= 0) u = rs[i] * __half2float(tcol[(size_t)j * QKVT_N]);
            acc = fmaf(a, acc, u);
        }
        #pragma unroll
        for (int i = 0; i < 64; i++) {
            float u = rs[64 + i] * __half2float(tcol[(size_t)(c0 + i) * QKVT_N]);
            us[i * 256 + tid] = __float2half(u);
            acc = fmaf(a, acc, u);
            fwd[i] = acc;
        }
        acc = 0.f;
        #pragma unroll
        for (int i = 63; i >= 0; i--) {
            int j = c0 + 64 + i;
            float u = 0.f;
            if (j < Nn) u = rs[128 + i] * __half2float(tcol[(size_t)j * QKVT_N]);
            acc = fmaf(a, acc, u);
        }
        #pragma unroll
        for (int i = 63; i >= 0; i--) {
            float prev = acc;
            ocol[(size_t)(c0 + i) * CAT_N] = __float2half(fwd[i] + a * prev);
            acc = fmaf(a, acc, __half2float(us[i * 256 + tid]));
        }
    }
}

// ---------------------------------------------------------------------------
extern "C" void kernel_launch(void* const* d_in, const int* in_sizes, int n_in,
                              void* d_out, int out_size)
{
    const float* x    = (const float*)d_in[0];   // [4,2048,512]
    const float* Wqkv = (const float*)d_in[1];   // [512,2048]
    const float* Wout = (const float*)d_in[2];   // [1024,512]
    const float* bout = (const float*)d_in[3];   // [512]
    float* out = (float*)d_out;                  // [4,2048,512]

    half *qkvt, *cat, *xh, *wqh, *woh;
    cudaGetSymbolAddress((void**)&qkvt, g_qkvt);
    cudaGetSymbolAddress((void**)&cat,  g_cat);
    cudaGetSymbolAddress((void**)&xh,   g_xh);
    cudaGetSymbolAddress((void**)&wqh,  g_wqh);
    cudaGetSymbolAddress((void**)&woh,  g_woh);

    // Convert all fp32 inputs to half (one launch)
    cvt_all<<<(Mn * Dn + Dn * QKVT_N + CAT_N * Dn) / 4 / 256, 256>>>(
        x, Wqkv, Wout);

    const int GS = 4 * GBUF;   // 208896 B dynamic smem, 1 CTA/SM
    cudaFuncSetAttribute(gemm_h2<half>,
                         cudaFuncAttributeMaxDynamicSharedMemorySize, GS);
    cudaFuncSetAttribute(gemm_h2<float>,
                         cudaFuncAttributeMaxDynamicSharedMemorySize, GS);
    cudaFuncSetAttribute(flash_scan,
                         cudaFuncAttributeMaxDynamicSharedMemorySize, FSM_BYTES);

    // GEMM1: QKVT(half) = Xh @ Wqkvh
    gemm_h2<half><<<dim3(QKVT_N / 256, Mn / 128), 256, GS>>>(
        xh, wqh, qkvt, nullptr, Mn, QKVT_N, Dn);

    // Branch 1 + Branch 2 fused: flash (blocks 0..511) + scan (512..767)
    flash_scan<<<768, 256, FSM_BYTES>>>(qkvt, cat);

    // GEMM2: out(float) = cat(half) @ Wouth + b_out
    gemm_h2<float><<<dim3(Dn / 256, Mn / 128), 256, GS>>>(
        cat, woh, out, bout, Mn, Dn, CAT_N);
}